// round 3
// baseline (speedup 1.0000x reference)
#include <cuda_runtime.h>

#define LSEQ  2048
#define BATCH 512
#define IN    78
#define NG    16

#define NSCAN_BLK   128           // 4 warps per block, 1 warp = 1 batch element
#define NGEMM_BLK   8192          // 128 rows each, 4 blocks per timestep
#define BLK_PER_SLAB 64           // 64 gemm blocks = 16 timesteps
#define NSLAB       128           // 8192 / 64

// 64 MiB scratch for precomputed, prescaled input gates, layout [t][b][u*4+e]
__device__ float g_xg[LSEQ * BATCH * NG];
__device__ int   g_ready[NSLAB];

__device__ __forceinline__ float ex2f(float x) {
    float r; asm("ex2.approx.f32 %0, %1;" : "=f"(r) : "f"(x)); return r;
}
__device__ __forceinline__ float rcpf(float x) {
    float r; asm("rcp.approx.f32 %0, %1;" : "=f"(r) : "f"(x)); return r;
}
__device__ __forceinline__ int ld_acq(const int* p) {
    int v; asm volatile("ld.acquire.gpu.global.b32 %0, [%1];" : "=r"(v) : "l"(p)); return v;
}

// sigmoid(x) = rcp(1 + ex2(-log2(e) * x))
// tanh(x)    = 1 - 2 * rcp(1 + ex2(+2*log2(e) * x))
#define SIG_SC  (-1.4426950408889634f)
#define TANH_SC ( 2.8853900817779268f)

__global__ void reset_kernel() {
    if (threadIdx.x < NSLAB) g_ready[threadIdx.x] = 0;
}

// ---------------------------------------------------------------------------
// GEMM producer: one block = 128 (t,b) rows of xg.
// xg[t][b][u*4+e] = scale_e * ( x[t][b] . W_ih0[e*4+u] + b_ih0 + b_hh0 )
// ---------------------------------------------------------------------------
__device__ __forceinline__ void gemm_block(
    int gbid,
    const float* __restrict__ x,
    const float* __restrict__ Wih0,
    const float* __restrict__ bih0,
    const float* __restrict__ bhh0)
{
    __shared__ float xs[128 * 79];
    __shared__ float ws[IN * NG];
    __shared__ float bs[NG];

    const int tid = threadIdx.x;
    const int rowbase = gbid * 128;
    const float* xsrc = x + rowbase * IN;

    for (int i = tid; i < 128 * IN; i += 256) {
        int r = i / IN;
        int d = i - r * IN;
        xs[r * 79 + d] = xsrc[i];
    }
    for (int i = tid; i < IN * NG; i += 256) {
        int d = i >> 4, n = i & 15;
        int u = n >> 2, e = n & 3;
        float sc = (e == 2) ? TANH_SC : SIG_SC;
        ws[i] = Wih0[(e * 4 + u) * IN + d] * sc;
    }
    if (tid < NG) {
        int u = tid >> 2, e = tid & 3;
        float sc = (e == 2) ? TANH_SC : SIG_SC;
        bs[tid] = (bih0[e * 4 + u] + bhh0[e * 4 + u]) * sc;
    }
    __syncthreads();

    const int r  = tid & 127;
    const int n0 = (tid >> 7) * 8;

    float acc0 = bs[n0 + 0], acc1 = bs[n0 + 1], acc2 = bs[n0 + 2], acc3 = bs[n0 + 3];
    float acc4 = bs[n0 + 4], acc5 = bs[n0 + 5], acc6 = bs[n0 + 6], acc7 = bs[n0 + 7];

    const float* xrow = xs + r * 79;
    #pragma unroll 13
    for (int d = 0; d < IN; d++) {
        float xv = xrow[d];
        float4 wa = *(const float4*)(ws + d * NG + n0);
        float4 wb = *(const float4*)(ws + d * NG + n0 + 4);
        acc0 = fmaf(xv, wa.x, acc0);
        acc1 = fmaf(xv, wa.y, acc1);
        acc2 = fmaf(xv, wa.z, acc2);
        acc3 = fmaf(xv, wa.w, acc3);
        acc4 = fmaf(xv, wb.x, acc4);
        acc5 = fmaf(xv, wb.y, acc5);
        acc6 = fmaf(xv, wb.z, acc6);
        acc7 = fmaf(xv, wb.w, acc7);
    }

    float4* outp = (float4*)(g_xg + (rowbase + r) * NG + n0);
    outp[0] = make_float4(acc0, acc1, acc2, acc3);
    outp[1] = make_float4(acc4, acc5, acc6, acc7);

    __syncthreads();
    if (tid == 0) {
        __threadfence();
        atomicAdd(&g_ready[gbid >> 6], 1);
    }
}

// ---------------------------------------------------------------------------
// Scan consumer: ONE WARP PER BATCH ELEMENT, one gate per lane.
//   lane = layer*16 + u*4 + e   (layer1 lags layer0 by one step)
// Each lane computes gate (u,e) of its layer; all 4 lanes of a unit
// redundantly carry (h, c) so state needs no extra communication.
// c carried pre-scaled by 2*log2(e); weights/biases/xg prescaled per gate.
// ---------------------------------------------------------------------------
__device__ __forceinline__ void scan_block(
    const float* __restrict__ Whh0,
    const float* __restrict__ Wih1,
    const float* __restrict__ Whh1,
    const float* __restrict__ bih1,
    const float* __restrict__ bhh1,
    const int*   __restrict__ lens,
    float*       __restrict__ out)
{
    const int tid = threadIdx.x;
    if (tid >= 128) return;
    const int lane  = tid & 31;
    const int b     = blockIdx.x * 4 + (tid >> 5);
    const int layer = lane >> 4;
    const int r     = lane & 15;
    const int u     = r >> 2;
    const int e     = r & 3;
    const int row   = e * 4 + u;
    const int gb    = lane & ~3;
    const float sc  = (e == 2) ? TANH_SC : SIG_SC;
    const int len   = lens[b];
    const bool doStore = (layer == 1) && (e == 0);

    float wA[4], wB[4];
    #pragma unroll
    for (int k = 0; k < 4; k++) {
        wA[k] = (layer ? Wih1[row * 4 + k] : Whh0[row * 4 + k]) * sc;
        wB[k] = layer ? Whh1[row * 4 + k] * sc : 0.0f;
    }
    const float bias = layer ? (bih1[row] + bhh1[row]) * sc : 0.0f;

    float h = 0.0f, cs = 0.0f;                 // cs = TANH_SC * c
    const float* xgb = g_xg + b * NG + r;      // + t*BATCH*NG per step
    float* outb = out + b * 4 + u;

    while (ld_acq(&g_ready[0]) < BLK_PER_SLAB) __nanosleep(64);

    float buf[4];
    #pragma unroll
    for (int j = 0; j < 4; j++)
        buf[j] = xgb[j * (BATCH * NG)];

    for (int n0 = 0; n0 < 2052; n0 += 4) {
        if ((n0 & 15) == 0) {
            int s = (n0 >> 4) + 1;
            s = (s > NSLAB - 1) ? (NSLAB - 1) : s;
            while (ld_acq(&g_ready[s]) < BLK_PER_SLAB) __nanosleep(64);
        }

        float nbuf[4];
        #pragma unroll
        for (int j = 0; j < 4; j++) {
            int t = n0 + 4 + j;
            t = (t > LSEQ - 1) ? (LSEQ - 1) : t;
            nbuf[j] = xgb[t * (BATCH * NG)];
        }

        #pragma unroll
        for (int j = 0; j < 4; j++) {
            const int n = n0 + j;

            // broadcast previous h: layer0 units from lanes 0/4/8/12,
            // layer1 units from lanes 16/20/24/28
            float hA0 = __shfl_sync(0xffffffffu, h, 0);
            float hA1 = __shfl_sync(0xffffffffu, h, 4);
            float hA2 = __shfl_sync(0xffffffffu, h, 8);
            float hA3 = __shfl_sync(0xffffffffu, h, 12);
            float hB0 = __shfl_sync(0xffffffffu, h, 16);
            float hB1 = __shfl_sync(0xffffffffu, h, 20);
            float hB2 = __shfl_sync(0xffffffffu, h, 24);
            float hB3 = __shfl_sync(0xffffffffu, h, 28);

            float base = layer ? bias : buf[j];
            float pa = fmaf(hA1, wA[1], hA0 * wA[0]);
            float pb = fmaf(hA3, wA[3], hA2 * wA[2]);
            float qa = fmaf(hB1, wB[1], hB0 * wB[0]);
            float qb = fmaf(hB3, wB[3], hB2 * wB[2]);
            float gate = base + ((pa + pb) + (qa + qb));
            float rr = rcpf(1.0f + ex2f(gate));   // sigmoid (or tanh half)

            // gather the 4 gate results of this unit
            float ri = __shfl_sync(0xffffffffu, rr, gb + 0);
            float rf = __shfl_sync(0xffffffffu, rr, gb + 1);
            float rg = __shfl_sync(0xffffffffu, rr, gb + 2);
            float ro = __shfl_sync(0xffffffffu, rr, gb + 3);

            float gsv = fmaf(-2.0f * TANH_SC, rg, TANH_SC);   // TANH_SC*tanh(g)
            float cn  = fmaf(rf, cs, ri * gsv);               // scaled c
            float tc  = fmaf(-2.0f, rcpf(1.0f + ex2f(cn)), 1.0f); // tanh(c)
            float hn  = ro * tc;

            // layer1 must not latch the n==0 (pre-history) step
            bool upd = (layer == 0) || (n >= 1);
            h  = upd ? hn : 0.0f;
            cs = upd ? cn : 0.0f;

            if (doStore && n >= 1 && n <= LSEQ) {
                int t = n - 1;
                outb[t * (BATCH * 4)] = (t < len) ? h : 0.0f;
            }
        }
        buf[0] = nbuf[0]; buf[1] = nbuf[1]; buf[2] = nbuf[2]; buf[3] = nbuf[3];
    }
}

// ---------------------------------------------------------------------------
// Fused kernel: blocks 0..127 = scan (wave 1 resident), rest = gemm.
// ---------------------------------------------------------------------------
__global__ void __launch_bounds__(256) fused_kernel(
    const float* __restrict__ x,
    const float* __restrict__ Wih0,
    const float* __restrict__ bih0,
    const float* __restrict__ bhh0,
    const float* __restrict__ Whh0,
    const float* __restrict__ Wih1,
    const float* __restrict__ Whh1,
    const float* __restrict__ bih1,
    const float* __restrict__ bhh1,
    const int*   __restrict__ lens,
    float*       __restrict__ out)
{
    if (blockIdx.x < NSCAN_BLK) {
        scan_block(Whh0, Wih1, Whh1, bih1, bhh1, lens, out);
    } else {
        gemm_block(blockIdx.x - NSCAN_BLK, x, Wih0, bih0, bhh0);
    }
}

extern "C" void kernel_launch(void* const* d_in, const int* in_sizes, int n_in,
                              void* d_out, int out_size)
{
    const float* x    = (const float*)d_in[0];
    const int*   lens = (const int*)  d_in[1];
    const float* Wih0 = (const float*)d_in[2];
    const float* Whh0 = (const float*)d_in[3];
    const float* bih0 = (const float*)d_in[4];
    const float* bhh0 = (const float*)d_in[5];
    const float* Wih1 = (const float*)d_in[6];
    const float* Whh1 = (const float*)d_in[7];
    const float* bih1 = (const float*)d_in[8];
    const float* bhh1 = (const float*)d_in[9];
    float* out = (float*)d_out;

    reset_kernel<<<1, 128>>>();
    fused_kernel<<<NSCAN_BLK + NGEMM_BLK, 256>>>(
        x, Wih0, bih0, bhh0, Whh0, Wih1, Whh1, bih1, bhh1, lens, out);
}

// round 4
// speedup vs baseline: 1.5175x; 1.5175x over previous
#include <cuda_runtime.h>

#define LSEQ  2048
#define BATCH 512
#define IN    78
#define NG    16

#define NSCAN_BLK   32            // 16 batches per block, 8 lanes per batch
#define NGEMM_BLK   8192          // 128 rows each, 4 blocks per timestep
#define BLK_PER_SLAB 64           // 64 gemm blocks = 16 timesteps
#define NSLAB       128           // 8192 / 64

// 64 MiB scratch for precomputed, prescaled input gates, layout [t][b][u*4+e]
__device__ float g_xg[LSEQ * BATCH * NG];
__device__ int   g_ready[NSLAB];

__device__ __forceinline__ float tanhf_a(float x) {
    float r; asm("tanh.approx.f32 %0, %1;" : "=f"(r) : "f"(x)); return r;
}
__device__ __forceinline__ int ld_acq(const int* p) {
    int v; asm volatile("ld.acquire.gpu.global.b32 %0, [%1];" : "=r"(v) : "l"(p)); return v;
}

// sigmoid(x) = 0.5 + 0.5*tanh(0.5*x)  -> prescale sigmoid-gate rows by 0.5
// tanh gate (e==2): no prescale.

__global__ void reset_kernel() {
    if (threadIdx.x < NSLAB) g_ready[threadIdx.x] = 0;
}

// ---------------------------------------------------------------------------
// GEMM producer: one block = 128 (t,b) rows of xg.
// xg[t][b][u*4+e] = scale_e * ( x[t][b] . W_ih0[e*4+u] + b_ih0 + b_hh0 )
// scale_e = 0.5 for sigmoid gates (e=0,1,3), 1.0 for the tanh gate (e=2).
// ---------------------------------------------------------------------------
__device__ __forceinline__ void gemm_block(
    int gbid,
    const float* __restrict__ x,
    const float* __restrict__ Wih0,
    const float* __restrict__ bih0,
    const float* __restrict__ bhh0)
{
    __shared__ float xs[128 * 79];
    __shared__ float ws[IN * NG];
    __shared__ float bs[NG];

    const int tid = threadIdx.x;
    const int rowbase = gbid * 128;
    const float* xsrc = x + rowbase * IN;

    for (int i = tid; i < 128 * IN; i += 256) {
        int r = i / IN;
        int d = i - r * IN;
        xs[r * 79 + d] = xsrc[i];
    }
    for (int i = tid; i < IN * NG; i += 256) {
        int d = i >> 4, n = i & 15;
        int u = n >> 2, e = n & 3;
        float sc = (e == 2) ? 1.0f : 0.5f;
        ws[i] = Wih0[(e * 4 + u) * IN + d] * sc;
    }
    if (tid < NG) {
        int u = tid >> 2, e = tid & 3;
        float sc = (e == 2) ? 1.0f : 0.5f;
        bs[tid] = (bih0[e * 4 + u] + bhh0[e * 4 + u]) * sc;
    }
    __syncthreads();

    const int r  = tid & 127;
    const int n0 = (tid >> 7) * 8;

    float acc0 = bs[n0 + 0], acc1 = bs[n0 + 1], acc2 = bs[n0 + 2], acc3 = bs[n0 + 3];
    float acc4 = bs[n0 + 4], acc5 = bs[n0 + 5], acc6 = bs[n0 + 6], acc7 = bs[n0 + 7];

    const float* xrow = xs + r * 79;
    #pragma unroll 13
    for (int d = 0; d < IN; d++) {
        float xv = xrow[d];
        float4 wa = *(const float4*)(ws + d * NG + n0);
        float4 wb = *(const float4*)(ws + d * NG + n0 + 4);
        acc0 = fmaf(xv, wa.x, acc0);
        acc1 = fmaf(xv, wa.y, acc1);
        acc2 = fmaf(xv, wa.z, acc2);
        acc3 = fmaf(xv, wa.w, acc3);
        acc4 = fmaf(xv, wb.x, acc4);
        acc5 = fmaf(xv, wb.y, acc5);
        acc6 = fmaf(xv, wb.z, acc6);
        acc7 = fmaf(xv, wb.w, acc7);
    }

    float4* outp = (float4*)(g_xg + (rowbase + r) * NG + n0);
    outp[0] = make_float4(acc0, acc1, acc2, acc3);
    outp[1] = make_float4(acc4, acc5, acc6, acc7);

    __syncthreads();
    if (tid == 0) {
        __threadfence();
        atomicAdd(&g_ready[gbid >> 6], 1);
    }
}

// ---------------------------------------------------------------------------
// Scan consumer: 8 lanes per batch element (round-2 layout):
//   lanes 0-3: layer0 hidden unit u   lanes 4-7: layer1 unit u (lagging 1 step)
// Each lane computes all 4 gates of its unit with MUFU.TANH activations:
//   sigmoid via prescaled-by-0.5 gate + 0.5 + 0.5*tanh folded into c/h update.
//   t_i,t_f,t_g,t_o = tanh(pre_gate)
//   cn = 0.5*((c + t_f*c) + (t_g + t_i*t_g))
//   hn = 0.5*(tc + t_o*tc),  tc = tanh(cn)
// ---------------------------------------------------------------------------
__device__ __forceinline__ void scan_block(
    const float* __restrict__ Whh0,
    const float* __restrict__ Wih1,
    const float* __restrict__ Whh1,
    const float* __restrict__ bih1,
    const float* __restrict__ bhh1,
    const int*   __restrict__ lens,
    float*       __restrict__ out)
{
    const int tid  = threadIdx.x;
    if (tid >= 128) return;
    const int lane = tid & 31;
    const int b    = blockIdx.x * 16 + (tid >> 3);
    const int u    = tid & 3;
    const bool isL1 = (tid & 4) != 0;
    const int len  = lens[b];

    float w1[4][4], w2[4][4], bias4[4];
    #pragma unroll
    for (int e = 0; e < 4; e++) {
        const float sc = (e == 2) ? 1.0f : 0.5f;
        const int row = e * 4 + u;
        bias4[e] = isL1 ? (bih1[row] + bhh1[row]) * sc : 0.0f;
        #pragma unroll
        for (int k = 0; k < 4; k++) {
            w1[e][k] = (isL1 ? Wih1[row * 4 + k] : Whh0[row * 4 + k]) * sc;
            w2[e][k] = isL1 ? Whh1[row * 4 + k] * sc : 0.0f;
        }
    }

    float h = 0.0f, c = 0.0f;
    const float4* xg4 = (const float4*)g_xg;
    const int bidx = b * 4 + u;
    const int gbase = lane & ~7;

    while (ld_acq(&g_ready[0]) < BLK_PER_SLAB) __nanosleep(64);

    float4 buf[4];
    #pragma unroll
    for (int j = 0; j < 4; j++)
        buf[j] = xg4[j * (BATCH * 4) + bidx];

    for (int n0 = 0; n0 < 2052; n0 += 4) {
        if ((n0 & 15) == 0) {
            int s = (n0 >> 4) + 1;
            s = (s > NSLAB - 1) ? (NSLAB - 1) : s;
            while (ld_acq(&g_ready[s]) < BLK_PER_SLAB) __nanosleep(64);
        }

        float4 nbuf[4];
        #pragma unroll
        for (int j = 0; j < 4; j++) {
            int t = n0 + 4 + j;
            t = (t > LSEQ - 1) ? (LSEQ - 1) : t;
            nbuf[j] = xg4[t * (BATCH * 4) + bidx];
        }

        #pragma unroll
        for (int j = 0; j < 4; j++) {
            const int n = n0 + j;

            float a0 = __shfl_sync(0xffffffffu, h, gbase + 0);
            float a1 = __shfl_sync(0xffffffffu, h, gbase + 1);
            float a2 = __shfl_sync(0xffffffffu, h, gbase + 2);
            float a3 = __shfl_sync(0xffffffffu, h, gbase + 3);
            float q0 = __shfl_sync(0xffffffffu, h, gbase + 4);
            float q1 = __shfl_sync(0xffffffffu, h, gbase + 5);
            float q2 = __shfl_sync(0xffffffffu, h, gbase + 6);
            float q3 = __shfl_sync(0xffffffffu, h, gbase + 7);

            float xb[4];
            xb[0] = buf[j].x; xb[1] = buf[j].y; xb[2] = buf[j].z; xb[3] = buf[j].w;

            float rr[4];
            #pragma unroll
            for (int e = 0; e < 4; e++) {
                float bse = isL1 ? bias4[e] : xb[e];
                float m01 = fmaf(a1, w1[e][1], a0 * w1[e][0]);
                float m23 = fmaf(a3, w1[e][3], a2 * w1[e][2]);
                float m45 = fmaf(q1, w2[e][1], q0 * w2[e][0]);
                float m67 = fmaf(q3, w2[e][3], q2 * w2[e][2]);
                float gate = bse + ((m01 + m23) + (m45 + m67));
                rr[e] = tanhf_a(gate);
            }
            float ti = rr[0], tf = rr[1], tg = rr[2], to = rr[3];
            float A  = fmaf(tf, c, c);        // c*(1+tanh(f/2)) = 2*sig(f)*c
            float Bv = fmaf(ti, tg, tg);      // tanh(g)*(1+tanh(i/2))
            float cn = 0.5f * (A + Bv);
            float tc = tanhf_a(cn);
            float hn = 0.5f * fmaf(to, tc, tc);

            bool upd = (!isL1) || (n >= 1);
            h = upd ? hn : 0.0f;
            c = upd ? cn : 0.0f;

            if (isL1 && n >= 1 && n <= LSEQ) {
                int t = n - 1;
                out[t * (BATCH * 4) + bidx] = (t < len) ? h : 0.0f;
            }
        }
        buf[0] = nbuf[0]; buf[1] = nbuf[1]; buf[2] = nbuf[2]; buf[3] = nbuf[3];
    }
}

// ---------------------------------------------------------------------------
// Fused kernel: blocks 0..31 = scan (wave 1 resident), rest = gemm.
// ---------------------------------------------------------------------------
__global__ void __launch_bounds__(256) fused_kernel(
    const float* __restrict__ x,
    const float* __restrict__ Wih0,
    const float* __restrict__ bih0,
    const float* __restrict__ bhh0,
    const float* __restrict__ Whh0,
    const float* __restrict__ Wih1,
    const float* __restrict__ Whh1,
    const float* __restrict__ bih1,
    const float* __restrict__ bhh1,
    const int*   __restrict__ lens,
    float*       __restrict__ out)
{
    if (blockIdx.x < NSCAN_BLK) {
        scan_block(Whh0, Wih1, Whh1, bih1, bhh1, lens, out);
    } else {
        gemm_block(blockIdx.x - NSCAN_BLK, x, Wih0, bih0, bhh0);
    }
}

extern "C" void kernel_launch(void* const* d_in, const int* in_sizes, int n_in,
                              void* d_out, int out_size)
{
    const float* x    = (const float*)d_in[0];
    const int*   lens = (const int*)  d_in[1];
    const float* Wih0 = (const float*)d_in[2];
    const float* Whh0 = (const float*)d_in[3];
    const float* bih0 = (const float*)d_in[4];
    const float* bhh0 = (const float*)d_in[5];
    const float* Wih1 = (const float*)d_in[6];
    const float* Whh1 = (const float*)d_in[7];
    const float* bih1 = (const float*)d_in[8];
    const float* bhh1 = (const float*)d_in[9];
    float* out = (float*)d_out;

    reset_kernel<<<1, 128>>>();
    fused_kernel<<<NSCAN_BLK + NGEMM_BLK, 256>>>(
        x, Wih0, bih0, bhh0, Whh0, Wih1, Whh1, bih1, bhh1, lens, out);
}